// round 15
// baseline (speedup 1.0000x reference)
#include <cuda_runtime.h>
#include <cuda_bf16.h>
#include <cstdint>

// ---------------- problem constants ----------------
#define N_STREAMS 8
#define D_MODEL   2048
#define NS        16
#define N_SKEW    120
#define KPAD      128
#define TOKENS    8192

#define TILE_M    32
#define HALF_M    16
#define M_TILES   (TOKENS / TILE_M)    // 256
#define KC        64                   // d per chunk
#define NC        32                   // chunks per half
#define NIT       64                   // total iterations (2 halves)
#define PITCH_B   144                  // bf16 row pitch bytes

#define THREADS   256

// smem layout (bytes):
//  raw stream staging: 2 bufs x (128 rows x 256B) = 65536
//  A mean tiles:       4 x (16 rows x 144B) = 9216   at 65536
//  B tiles (single):   2 x (128 rows x 144B) = 36864 at 74752
//  bias:               512                            at 111616
#define RAW_OFF(buf)    ((buf) * 32768)
#define A_OFF(buf, hl)  (65536 + ((buf) * 2 + (hl)) * 2304)
#define B_OFF(hl)       (74752 + (hl) * 18432)
#define BIAS_OFF        111616
#define SMEM_TOTAL      112128

// named barriers: 1,2=FULL[par]; 3,4=EMPTY_A[par]; 5=EMPTY_B; 6=producer-publish
#define BAR_SYNC(id)    asm volatile("bar.sync %0, 256;"   :: "r"(id) : "memory")
#define BAR_ARRIVE(id)  asm volatile("bar.arrive %0, 256;" :: "r"(id) : "memory")
#define BAR_PROD()      asm volatile("bar.sync 6, 128;" ::: "memory")

#define CP_ASYNC(dst, src) \
    asm volatile("cp.async.cg.shared.global [%0], [%1], 16;" \
                 :: "r"(dst), "l"(src) : "memory")
#define CP_COMMIT() asm volatile("cp.async.commit_group;" ::: "memory")
#define CP_WAIT1()  asm volatile("cp.async.wait_group 1;" ::: "memory")
#define CP_WAIT0()  asm volatile("cp.async.wait_group 0;" ::: "memory")

// ---------------- device scratch ----------------
__device__ __nv_bfloat16 g_Whi[KPAD * D_MODEL];   // 512 KB
__device__ __nv_bfloat16 g_Wlo[KPAD * D_MODEL];   // 512 KB

// ---------------- K0: W -> bf16 hi/lo (padded to 128 rows) ----------------
__global__ void prep_wt_kernel(const float* __restrict__ W) {
    int id = blockIdx.x * 256 + threadIdx.x;
    int k = id >> 11, d = id & (D_MODEL - 1);
    float v = (k < N_SKEW) ? W[k * D_MODEL + d] : 0.f;
    __nv_bfloat16 hi = __float2bfloat16(v);
    __nv_bfloat16 lo = __float2bfloat16(v - __bfloat162float(hi));
    g_Whi[id] = hi;
    g_Wlo[id] = lo;
}

// ---------------- fused kernel ----------------
__device__ __forceinline__ void mma16816(float c[4], const uint32_t a[4],
                                         uint32_t b0, uint32_t b1) {
    asm volatile(
        "mma.sync.aligned.m16n8k16.row.col.f32.bf16.bf16.f32 "
        "{%0,%1,%2,%3}, {%4,%5,%6,%7}, {%8,%9}, {%0,%1,%2,%3};"
        : "+f"(c[0]), "+f"(c[1]), "+f"(c[2]), "+f"(c[3])
        : "r"(a[0]), "r"(a[1]), "r"(a[2]), "r"(a[3]), "r"(b0), "r"(b1));
}

// issue cp.async for raw streams of iteration iq (16 ops per thread, no staging)
__device__ __forceinline__ void issue_raw(uint32_t raw_base,
                                          const float* __restrict__ streams,
                                          int tok0, int iq, int ptid) {
    const int half = iq >> 5;
    const int d0   = (iq & 31) * KC;
    const float* base = streams
        + (size_t)(tok0 + half * HALF_M) * (N_STREAMS * D_MODEL) + d0;
    #pragma unroll
    for (int j = 0; j < 16; j++) {
        int idx = ptid + j * 128;
        int row = idx >> 4;            // 0..127 = tk*8 + n
        int sl  = idx & 15;
        int tk = row >> 3, n = row & 7;
        const float* g = base + ((size_t)tk * N_STREAMS + n) * D_MODEL + sl * 4;
        uint32_t dst = raw_base + row * 256 + ((sl ^ n) << 4);  // xor swizzle
        CP_ASYNC(dst, g);
    }
}

// convert raw buffer rbuf -> A mean tile abuf (hi/lo bf16)
__device__ __forceinline__ void convert_raw(char* smem, int rbuf, int abuf, int ptid) {
    #pragma unroll
    for (int m = 0; m < 2; m++) {
        int idx = ptid + m * 128;
        int tk = idx >> 4, s = idx & 15;
        float4 v[N_STREAMS];
        #pragma unroll
        for (int n = 0; n < N_STREAMS; n++)
            v[n] = *reinterpret_cast<const float4*>(
                smem + RAW_OFF(rbuf) + (tk * 8 + n) * 256 + ((s ^ n) << 4));
        #pragma unroll
        for (int st = N_STREAMS / 2; st > 0; st >>= 1)
            #pragma unroll
            for (int n = 0; n < st; n++) {
                v[n].x += v[n+st].x; v[n].y += v[n+st].y;
                v[n].z += v[n+st].z; v[n].w += v[n+st].w;
            }
        float f[4] = { v[0].x*0.125f, v[0].y*0.125f, v[0].z*0.125f, v[0].w*0.125f };
        __nv_bfloat16 hi[4], lo[4];
        #pragma unroll
        for (int i = 0; i < 4; i++) {
            hi[i] = __float2bfloat16(f[i]);
            lo[i] = __float2bfloat16(f[i] - __bfloat162float(hi[i]));
        }
        *reinterpret_cast<uint2*>(smem + A_OFF(abuf,0) + tk * PITCH_B + s * 8) =
            *reinterpret_cast<uint2*>(hi);
        *reinterpret_cast<uint2*>(smem + A_OFF(abuf,1) + tk * PITCH_B + s * 8) =
            *reinterpret_cast<uint2*>(lo);
    }
}

__device__ __forceinline__ void load_b_regs(uint4 breg[16], int d0, int ptid) {
    #pragma unroll
    for (int p = 0; p < 16; p++) {
        int idx = ptid + p * 128;          // 0..2047
        int hl = idx >> 10;
        int rr = (idx & 1023) >> 3;
        int qq = idx & 7;
        const __nv_bfloat16* src = (hl ? g_Wlo : g_Whi)
                                 + (size_t)rr * D_MODEL + d0 + qq * 8;
        breg[p] = *reinterpret_cast<const uint4*>(src);
    }
}

__device__ __forceinline__ void store_b_regs(char* smem, const uint4 breg[16], int ptid) {
    #pragma unroll
    for (int p = 0; p < 16; p++) {
        int idx = ptid + p * 128;
        int hl = idx >> 10;
        int rr = (idx & 1023) >> 3;
        int qq = idx & 7;
        *reinterpret_cast<uint4*>(smem + B_OFF(hl) + rr * PITCH_B + qq * 16) = breg[p];
    }
}

__global__ void __launch_bounds__(THREADS, 2)
gomhc_fused_kernel(const float* __restrict__ streams,
                   const float* __restrict__ bias,
                   float* __restrict__ out) {
    extern __shared__ char smem[];
    uint32_t smem_b32;
    asm("{ .reg .u64 t; cvta.to.shared.u64 t, %1; cvt.u32.u64 %0, t; }"
        : "=r"(smem_b32) : "l"(smem));
    const int tid  = threadIdx.x;
    const int wid  = tid >> 5;
    const int lane = tid & 31;
    const int tok0 = blockIdx.x * TILE_M;

    if (tid < KPAD)
        *reinterpret_cast<float*>(smem + BIAS_OFF + tid * 4) =
            (tid < N_SKEW) ? bias[tid] : 0.f;

    const bool producer = (wid >= 4);

    if (producer) {
        const int ptid = tid - 128;
        // prologue: raw(0), raw(1) in flight; build iter 0
        issue_raw(smem_b32 + RAW_OFF(0), streams, tok0, 0, ptid); CP_COMMIT();
        issue_raw(smem_b32 + RAW_OFF(1), streams, tok0, 1, ptid); CP_COMMIT();
        CP_WAIT1();           // raw(0) landed
        BAR_PROD();           // publish cross-thread
        convert_raw(smem, 0, 0, ptid);
        {
            uint4 breg[16];
            load_b_regs(breg, 0, ptid);
            store_b_regs(smem, breg, ptid);
        }
        BAR_ARRIVE(1);        // FULL parity 0

        #pragma unroll 1
        for (int ip = 1; ip < NIT; ip++) {
            if (ip + 1 < NIT) {
                issue_raw(smem_b32 + RAW_OFF((ip + 1) & 1), streams, tok0, ip + 1, ptid);
                CP_COMMIT();
                CP_WAIT1();   // raw(ip) landed
            } else {
                CP_WAIT0();   // raw(63) landed
            }
            BAR_PROD();       // publish
            if (ip >= 2) BAR_SYNC(3 + (ip & 1));   // EMPTY_A: A-buf free
            convert_raw(smem, ip & 1, ip & 1, ptid);
            uint4 breg[16];
            load_b_regs(breg, (ip & 31) * KC, ptid);
            BAR_SYNC(5);      // EMPTY_B: consumers done with previous B
            store_b_regs(smem, breg, ptid);
            BAR_ARRIVE(1 + (ip & 1));              // FULL
        }
    } else {
        // ---- consumer: 4 warps, 16 rows x 32 cols each, acc per half ----
        const int g  = lane >> 2;
        const int t  = lane & 3;
        const int wn = wid * 32;
        float acc[2][4][4];
        #pragma unroll
        for (int h = 0; h < 2; h++)
            #pragma unroll
            for (int nt = 0; nt < 4; nt++)
                #pragma unroll
                for (int i = 0; i < 4; i++) acc[h][nt][i] = 0.f;

        #pragma unroll
        for (int half = 0; half < 2; half++) {
            #pragma unroll 1
            for (int c = 0; c < NC; c++) {
                const int buf = c & 1;
                BAR_SYNC(1 + buf);         // FULL
                const char* pah = smem + A_OFF(buf, 0);
                const char* pal = smem + A_OFF(buf, 1);
                const char* pbh = smem + B_OFF(0);
                const char* pbl = smem + B_OFF(1);
                #pragma unroll
                for (int ks = 0; ks < 4; ks++) {
                    const int kb = ks * 16 + 2 * t;
                    uint32_t Ah[4], Al[4];
                    Ah[0] = *reinterpret_cast<const uint32_t*>(pah + (g    ) * PITCH_B + kb * 2);
                    Ah[1] = *reinterpret_cast<const uint32_t*>(pah + (g + 8) * PITCH_B + kb * 2);
                    Ah[2] = *reinterpret_cast<const uint32_t*>(pah + (g    ) * PITCH_B + (kb + 8) * 2);
                    Ah[3] = *reinterpret_cast<const uint32_t*>(pah + (g + 8) * PITCH_B + (kb + 8) * 2);
                    Al[0] = *reinterpret_cast<const uint32_t*>(pal + (g    ) * PITCH_B + kb * 2);
                    Al[1] = *reinterpret_cast<const uint32_t*>(pal + (g + 8) * PITCH_B + kb * 2);
                    Al[2] = *reinterpret_cast<const uint32_t*>(pal + (g    ) * PITCH_B + (kb + 8) * 2);
                    Al[3] = *reinterpret_cast<const uint32_t*>(pal + (g + 8) * PITCH_B + (kb + 8) * 2);
                    #pragma unroll
                    for (int nt = 0; nt < 4; nt++) {
                        int n0 = wn + nt * 8 + g;
                        uint32_t bh0 = *reinterpret_cast<const uint32_t*>(pbh + n0 * PITCH_B + kb * 2);
                        uint32_t bh1 = *reinterpret_cast<const uint32_t*>(pbh + n0 * PITCH_B + (kb + 8) * 2);
                        uint32_t bl0 = *reinterpret_cast<const uint32_t*>(pbl + n0 * PITCH_B + kb * 2);
                        uint32_t bl1 = *reinterpret_cast<const uint32_t*>(pbl + n0 * PITCH_B + (kb + 8) * 2);
                        mma16816(acc[half][nt], Ah, bh0, bh1);
                        mma16816(acc[half][nt], Ah, bl0, bl1);
                        mma16816(acc[half][nt], Al, bh0, bh1);
                    }
                }
                BAR_ARRIVE(3 + buf);       // EMPTY_A
                BAR_ARRIVE(5);             // EMPTY_B
            }
        }

        __syncthreads();                   // join producers

        // epilogue: z -> smem (alias over raw region)
        float* zs = reinterpret_cast<float*>(smem);    // [32][128]
        #pragma unroll
        for (int half = 0; half < 2; half++)
            #pragma unroll
            for (int nt = 0; nt < 4; nt++) {
                int row = half * 16 + g;
                int col = wn + nt * 8 + 2 * t;
                *reinterpret_cast<float2*>(&zs[row * KPAD + col]) =
                    make_float2(acc[half][nt][0], acc[half][nt][1]);
                *reinterpret_cast<float2*>(&zs[(row + 8) * KPAD + col]) =
                    make_float2(acc[half][nt][2], acc[half][nt][3]);
            }
    }

    if (producer) __syncthreads();          // matching join for producers
    __syncthreads();                        // zs visible to all

    // =================== solve: 8 warps x 2 passes x 2 tokens = 32 ===================
    {
        float* zs = reinterpret_cast<float*>(smem);
        const float* bs = reinterpret_cast<const float*>(smem + BIAS_OFF);
        const int half = lane >> 4;
        const int r    = lane & 15;
        const unsigned mask = 0xffffffffu;

        #pragma unroll 1
        for (int pass = 0; pass < 2; pass++) {
            const int tk = wid * 4 + pass * 2 + half;   // 0..31
            const float* zt = zs + tk * KPAD;

            float m[32];
            #pragma unroll
            for (int cc = 0; cc < NS; cc++) {
                float a = 0.f;
                if (cc > r) {
                    int u = (r * (31 - r)) / 2 + (cc - r - 1);
                    a = zt[u] + bs[u];
                } else if (cc < r) {
                    int u = (cc * (31 - cc)) / 2 + (r - cc - 1);
                    a = -(zt[u] + bs[u]);
                }
                float diag = (cc == r) ? 1.f : 0.f;
                m[cc]      = diag + a;
                m[16 + cc] = diag - a;
            }

            #pragma unroll
            for (int i = 0; i < NS; i++) {
                const int src = i + (half << 4);
                float pivi = __shfl_sync(mask, m[i], src);
                float rp = 1.0f / pivi;
                float cf = (r == i) ? (1.0f - rp) : m[i] * rp;
                #pragma unroll
                for (int k = 0; k < 32; k++) {
                    float pk = __shfl_sync(mask, m[k], src);
                    m[k] = fmaf(-cf, pk, m[k]);
                }
            }

            float hq[8];
            #pragma unroll
            for (int q = 0; q < 8; q++) {
                float q0 = m[16 + 2 * q], q1 = m[16 + 2 * q + 1];
                hq[q] = q0 * q0 + q1 * q1;
            }
            #pragma unroll
            for (int q = 0; q < 8; q++)
                hq[q] += __shfl_xor_sync(mask, hq[q], 1);

            if (!(r & 1)) {
                const int tok = tok0 + tk;
                float* o = out + (size_t)tok * 64 + (r >> 1) * 8;
                #pragma unroll
                for (int q = 0; q < 8; q++) o[q] = 0.5f * hq[q];
            }
        }
    }
}

// ---------------- launch ----------------
extern "C" void kernel_launch(void* const* d_in, const int* in_sizes, int n_in,
                              void* d_out, int out_size) {
    const float* streams = (const float*)d_in[0];
    const float* W       = (const float*)d_in[1];
    const float* b       = (const float*)d_in[2];
    float* out = (float*)d_out;

    prep_wt_kernel<<<(KPAD * D_MODEL) / 256, 256>>>(W);

    cudaFuncSetAttribute(gomhc_fused_kernel,
                         cudaFuncAttributeMaxDynamicSharedMemorySize, SMEM_TOTAL);
    gomhc_fused_kernel<<<M_TILES, THREADS, SMEM_TOTAL>>>(streams, b, out);
}

// round 16
// speedup vs baseline: 1.1686x; 1.1686x over previous
#include <cuda_runtime.h>
#include <cuda_bf16.h>
#include <cstdint>

// ---------------- problem constants ----------------
#define N_STREAMS 8
#define D_MODEL   2048
#define NS        16
#define N_SKEW    120
#define KPAD      128
#define TOKENS    8192

#define TILE_M    32
#define M_TILES   (TOKENS / TILE_M)    // 256
#define KC        64                   // d per chunk
#define NC        (D_MODEL / KC)       // 32 chunks
#define PITCH_B   144                  // A-tile row pitch bytes (72 bf16)

#define THREADS   256

// smem: A mean tiles quad-buffered: 4 bufs x 2 (hi/lo) x (32 rows x 144B)
#define A_OFF(buf, hl) (((buf) * 2 + (hl)) * 4608)
#define BIAS_OFF 36864
#define SMEM_TOTAL (BIAS_OFF + 512)    // 37376; x2 CTAs = 74752 < 228K

// named barriers: FULL[b] = 1+b (b=0..3), EMPTY[b] = 5+b
#define BAR_SYNC(id)   asm volatile("bar.sync %0, 256;"   :: "r"(id) : "memory")
#define BAR_ARRIVE(id) asm volatile("bar.arrive %0, 256;" :: "r"(id) : "memory")

#define ADD2(d, a, b) \
    asm("add.rn.f32x2 %0, %1, %2;" : "=l"(d) : "l"(a), "l"(b))

// ---------------- device scratch ----------------
__device__ __nv_bfloat16 g_Whi[KPAD * D_MODEL];   // 512 KB
__device__ __nv_bfloat16 g_Wlo[KPAD * D_MODEL];   // 512 KB

// ---------------- K0: W -> bf16 hi/lo (padded to 128 rows) ----------------
__global__ void prep_wt_kernel(const float* __restrict__ W) {
    int id = blockIdx.x * 256 + threadIdx.x;
    int k = id >> 11, d = id & (D_MODEL - 1);
    float v = (k < N_SKEW) ? W[k * D_MODEL + d] : 0.f;
    __nv_bfloat16 hi = __float2bfloat16(v);
    __nv_bfloat16 lo = __float2bfloat16(v - __bfloat162float(hi));
    g_Whi[id] = hi;
    g_Wlo[id] = lo;
}

// ---------------- fused kernel ----------------
__device__ __forceinline__ void mma16816(float c[4], const uint32_t a[4],
                                         uint32_t b0, uint32_t b1) {
    asm volatile(
        "mma.sync.aligned.m16n8k16.row.col.f32.bf16.bf16.f32 "
        "{%0,%1,%2,%3}, {%4,%5,%6,%7}, {%8,%9}, {%0,%1,%2,%3};"
        : "+f"(c[0]), "+f"(c[1]), "+f"(c[2]), "+f"(c[3])
        : "r"(a[0]), "r"(a[1]), "r"(a[2]), "r"(a[3]), "r"(b0), "r"(b1));
}

// hi/lo split of a float pair -> (bf16x2 hi, bf16x2 lo), element0 in low half
__device__ __forceinline__ uint2 cvt_hilo(float f0, float f1) {
    uint32_t h, l;
    asm("cvt.rn.bf16x2.f32 %0, %1, %2;" : "=r"(h) : "f"(f1), "f"(f0));
    float h0 = __uint_as_float(h << 16);
    float h1 = __uint_as_float(h & 0xffff0000u);
    float l0 = f0 - h0, l1 = f1 - h1;
    asm("cvt.rn.bf16x2.f32 %0, %1, %2;" : "=r"(l) : "f"(l1), "f"(l0));
    return make_uint2(h, l);
}

// producer: stage A mean tile of one chunk into buffer buf; ptid in [0,128)
// 4 (token,slot) items; 2 staged at a time (16 LDG.128 in flight).
__device__ __forceinline__ void produce_chunk(
    char* smem, const float* __restrict__ streams,
    int tok0, int d0, int buf, int ptid) {
    #pragma unroll
    for (int ph = 0; ph < 2; ph++) {
        int idx0  = ptid + (2 * ph) * 128;
        int idx1  = idx0 + 128;
        int tk0i  = idx0 >> 4, sl0 = idx0 & 15;
        int tk1i  = idx1 >> 4, sl1 = idx1 & 15;
        const float4* s0 = reinterpret_cast<const float4*>(streams)
            + ((size_t)(tok0 + tk0i) * N_STREAMS * D_MODEL + d0) / 4 + sl0;
        const float4* s1 = reinterpret_cast<const float4*>(streams)
            + ((size_t)(tok0 + tk1i) * N_STREAMS * D_MODEL + d0) / 4 + sl1;
        float4 v[N_STREAMS], u[N_STREAMS];
        #pragma unroll
        for (int n = 0; n < N_STREAMS; n++) {
            v[n] = s0[n * (D_MODEL / 4)];
            u[n] = s1[n * (D_MODEL / 4)];
        }
        // packed f32x2 reduction trees
        unsigned long long va[N_STREAMS], vb[N_STREAMS], ua[N_STREAMS], ub[N_STREAMS];
        #pragma unroll
        for (int n = 0; n < N_STREAMS; n++) {
            va[n] = *reinterpret_cast<unsigned long long*>(&v[n].x);
            vb[n] = *reinterpret_cast<unsigned long long*>(&v[n].z);
            ua[n] = *reinterpret_cast<unsigned long long*>(&u[n].x);
            ub[n] = *reinterpret_cast<unsigned long long*>(&u[n].z);
        }
        #pragma unroll
        for (int s = N_STREAMS / 2; s > 0; s >>= 1)
            #pragma unroll
            for (int n = 0; n < s; n++) {
                ADD2(va[n], va[n], va[n+s]);
                ADD2(vb[n], vb[n], vb[n+s]);
                ADD2(ua[n], ua[n], ua[n+s]);
                ADD2(ub[n], ub[n], ub[n+s]);
            }
        float2 fva = *reinterpret_cast<float2*>(&va[0]);
        float2 fvb = *reinterpret_cast<float2*>(&vb[0]);
        float2 fua = *reinterpret_cast<float2*>(&ua[0]);
        float2 fub = *reinterpret_cast<float2*>(&ub[0]);
        uint2 c0 = cvt_hilo(fva.x * 0.125f, fva.y * 0.125f);
        uint2 c1 = cvt_hilo(fvb.x * 0.125f, fvb.y * 0.125f);
        uint2 d0c = cvt_hilo(fua.x * 0.125f, fua.y * 0.125f);
        uint2 d1c = cvt_hilo(fub.x * 0.125f, fub.y * 0.125f);
        *reinterpret_cast<uint2*>(smem + A_OFF(buf,0) + tk0i * PITCH_B + sl0 * 8) =
            make_uint2(c0.x, c1.x);
        *reinterpret_cast<uint2*>(smem + A_OFF(buf,1) + tk0i * PITCH_B + sl0 * 8) =
            make_uint2(c0.y, c1.y);
        *reinterpret_cast<uint2*>(smem + A_OFF(buf,0) + tk1i * PITCH_B + sl1 * 8) =
            make_uint2(d0c.x, d1c.x);
        *reinterpret_cast<uint2*>(smem + A_OFF(buf,1) + tk1i * PITCH_B + sl1 * 8) =
            make_uint2(d0c.y, d1c.y);
    }
}

__global__ void __launch_bounds__(THREADS, 2)
gomhc_fused_kernel(const float* __restrict__ streams,
                   const float* __restrict__ bias,
                   float* __restrict__ out) {
    extern __shared__ char smem[];
    const int tid  = threadIdx.x;
    const int wid  = tid >> 5;
    const int lane = tid & 31;
    const int tok0 = blockIdx.x * TILE_M;

    if (tid < KPAD)
        *reinterpret_cast<float*>(smem + BIAS_OFF + tid * 4) =
            (tid < N_SKEW) ? bias[tid] : 0.f;

    const bool producer = (wid >= 4);

    if (producer) {
        // producer: quad-buffer ring, 3-chunk runway
        const int ptid = tid - 128;
        #pragma unroll 1
        for (int c = 0; c < NC; c++) {
            if (c >= 4) BAR_SYNC(5 + (c & 3));     // EMPTY[buf]
            produce_chunk(smem, streams, tok0, c * KC, c & 3, ptid);
            BAR_ARRIVE(1 + (c & 3));               // FULL[buf]
        }
        __syncthreads();                           // join consumers
    } else {
        // consumer: 4 warps; A from smem, B直接 from global (L1-resident)
        const int g  = lane >> 2;
        const int t  = lane & 3;
        const int wn = wid * 32;
        float acc[2][4][4];
        #pragma unroll
        for (int mt = 0; mt < 2; mt++)
            #pragma unroll
            for (int nt = 0; nt < 4; nt++)
                #pragma unroll
                for (int i = 0; i < 4; i++) acc[mt][nt][i] = 0.f;

        #pragma unroll 1
        for (int c = 0; c < NC; c++) {
            const int buf = c & 3;
            BAR_SYNC(1 + buf);                     // FULL[buf]
            const char* pah = smem + A_OFF(buf, 0);
            const char* pal = smem + A_OFF(buf, 1);
            const int d0 = c * KC;
            #pragma unroll
            for (int ks = 0; ks < 4; ks++) {
                const int kb = ks * 16 + 2 * t;    // element col within chunk
                uint32_t Ah[2][4], Al[2][4];
                #pragma unroll
                for (int mt = 0; mt < 2; mt++) {
                    int r0 = mt * 16 + g;
                    Ah[mt][0] = *reinterpret_cast<const uint32_t*>(pah + (r0    ) * PITCH_B + kb * 2);
                    Ah[mt][1] = *reinterpret_cast<const uint32_t*>(pah + (r0 + 8) * PITCH_B + kb * 2);
                    Ah[mt][2] = *reinterpret_cast<const uint32_t*>(pah + (r0    ) * PITCH_B + (kb + 8) * 2);
                    Ah[mt][3] = *reinterpret_cast<const uint32_t*>(pah + (r0 + 8) * PITCH_B + (kb + 8) * 2);
                    Al[mt][0] = *reinterpret_cast<const uint32_t*>(pal + (r0    ) * PITCH_B + kb * 2);
                    Al[mt][1] = *reinterpret_cast<const uint32_t*>(pal + (r0 + 8) * PITCH_B + kb * 2);
                    Al[mt][2] = *reinterpret_cast<const uint32_t*>(pal + (r0    ) * PITCH_B + (kb + 8) * 2);
                    Al[mt][3] = *reinterpret_cast<const uint32_t*>(pal + (r0 + 8) * PITCH_B + (kb + 8) * 2);
                }
                #pragma unroll
                for (int nt = 0; nt < 4; nt++) {
                    int n0 = wn + nt * 8 + g;
                    size_t base = (size_t)n0 * D_MODEL + d0 + kb;
                    uint32_t bh0 = *reinterpret_cast<const uint32_t*>(&g_Whi[base]);
                    uint32_t bh1 = *reinterpret_cast<const uint32_t*>(&g_Whi[base + 8]);
                    uint32_t bl0 = *reinterpret_cast<const uint32_t*>(&g_Wlo[base]);
                    uint32_t bl1 = *reinterpret_cast<const uint32_t*>(&g_Wlo[base + 8]);
                    #pragma unroll
                    for (int mt = 0; mt < 2; mt++) {
                        mma16816(acc[mt][nt], Ah[mt], bh0, bh1);
                        mma16816(acc[mt][nt], Ah[mt], bl0, bl1);
                        mma16816(acc[mt][nt], Al[mt], bh0, bh1);
                    }
                }
            }
            BAR_ARRIVE(5 + buf);                   // EMPTY[buf]
        }

        __syncthreads();                           // join producers

        // epilogue: z -> smem (alias over A region, 16 KB)
        float* zs = reinterpret_cast<float*>(smem);
        #pragma unroll
        for (int mt = 0; mt < 2; mt++)
            #pragma unroll
            for (int nt = 0; nt < 4; nt++) {
                int row = mt * 16 + g;
                int col = wn + nt * 8 + 2 * t;
                *reinterpret_cast<float2*>(&zs[row * KPAD + col]) =
                    make_float2(acc[mt][nt][0], acc[mt][nt][1]);
                *reinterpret_cast<float2*>(&zs[(row + 8) * KPAD + col]) =
                    make_float2(acc[mt][nt][2], acc[mt][nt][3]);
            }
    }
    __syncthreads();                               // zs visible to all

    // =================== solve: 8 warps x 2 passes x 2 tokens = 32 ===================
    {
        float* zs = reinterpret_cast<float*>(smem);
        const float* bs = reinterpret_cast<const float*>(smem + BIAS_OFF);
        const int half = lane >> 4;
        const int r    = lane & 15;
        const unsigned mask = 0xffffffffu;

        #pragma unroll 1
        for (int pass = 0; pass < 2; pass++) {
            const int tk = wid * 4 + pass * 2 + half;   // 0..31
            const float* zt = zs + tk * KPAD;

            float m[32];
            #pragma unroll
            for (int cc = 0; cc < NS; cc++) {
                float a = 0.f;
                if (cc > r) {
                    int u = (r * (31 - r)) / 2 + (cc - r - 1);
                    a = zt[u] + bs[u];
                } else if (cc < r) {
                    int u = (cc * (31 - cc)) / 2 + (r - cc - 1);
                    a = -(zt[u] + bs[u]);
                }
                float diag = (cc == r) ? 1.f : 0.f;
                m[cc]      = diag + a;
                m[16 + cc] = diag - a;
            }

            #pragma unroll
            for (int i = 0; i < NS; i++) {
                const int src = i + (half << 4);
                float pivi = __shfl_sync(mask, m[i], src);
                float rp = 1.0f / pivi;
                float cf = (r == i) ? (1.0f - rp) : m[i] * rp;
                #pragma unroll
                for (int k = 0; k < 32; k++) {
                    float pk = __shfl_sync(mask, m[k], src);
                    m[k] = fmaf(-cf, pk, m[k]);
                }
            }

            float hq[8];
            #pragma unroll
            for (int q = 0; q < 8; q++) {
                float q0 = m[16 + 2 * q], q1 = m[16 + 2 * q + 1];
                hq[q] = q0 * q0 + q1 * q1;
            }
            #pragma unroll
            for (int q = 0; q < 8; q++)
                hq[q] += __shfl_xor_sync(mask, hq[q], 1);

            if (!(r & 1)) {
                const int tok = tok0 + tk;
                float* o = out + (size_t)tok * 64 + (r >> 1) * 8;
                #pragma unroll
                for (int q = 0; q < 8; q++) o[q] = 0.5f * hq[q];
            }
        }
    }
}

// ---------------- launch ----------------
extern "C" void kernel_launch(void* const* d_in, const int* in_sizes, int n_in,
                              void* d_out, int out_size) {
    const float* streams = (const float*)d_in[0];
    const float* W       = (const float*)d_in[1];
    const float* b       = (const float*)d_in[2];
    float* out = (float*)d_out;

    prep_wt_kernel<<<(KPAD * D_MODEL) / 256, 256>>>(W);

    cudaFuncSetAttribute(gomhc_fused_kernel,
                         cudaFuncAttributeMaxDynamicSharedMemorySize, SMEM_TOTAL);
    gomhc_fused_kernel<<<M_TILES, THREADS, SMEM_TOTAL>>>(streams, b, out);
}